// round 15
// baseline (speedup 1.0000x reference)
#include <cuda_runtime.h>
#include <cuda_fp16.h>
#include <cstdint>

#define MAXN 50000
#define MAXE 800000
#define HP   132
#define LDA  136    // fp16 row stride for A/B smem tiles (conflict-free)

// ---------------- scratch (device globals; no allocation allowed) ----------
__device__ __align__(16) __half g_h1[MAXN * 128];  // (x@W1)*norm_src, fp16
__device__ __align__(16) float g_h2[MAXN * 128];   // relu(agg1*norm_dst + b1)
__device__ __align__(16) float g_h3[MAXN * 8];
__device__ __align__(16) float g_nodeout[MAXN * 8];
__device__ __align__(16) __half g_w1img[128 * LDA];  // W1^T fp16 [n][k], padded
__device__ int   g_deg_out[MAXN];   // zeroed by k_pool tail each run
__device__ int   g_deg_in[MAXN];    // zeroed by k_pool tail each run
__device__ float g_norm_src[MAXN];
__device__ float g_norm_dst[MAXN];
__device__ int   g_off[MAXN];
__device__ int   g_cursor[MAXN];
__device__ int   g_csr_src[MAXE];
__device__ int   g_partial[256];      // scan flags: value+1; reset by fill block 0
__device__ unsigned g_deg_done;       // completion counters; reset by k_pool
__device__ unsigned g_scan_done;

// ---- k_graph: deg atomics -> scan(+norms) -> CSR fill, one launch ----------
// Block ranges (IDs ascending = scheduling order, so pollers always follow
// their producers): [0,nbe)=deg, nbe=W1 image, [nbe+1,nbe+1+nbscan)=scan,
// [nbe+1+nbscan, nbe+1+nbscan+nbe)=fill.
__global__ void __launch_bounds__(256)
k_graph(const float* __restrict__ W1, const int* __restrict__ src,
        const int* __restrict__ dst, int n, int e, int nbe, int nbscan) {
    __shared__ int ws[8];
    __shared__ int ws2[8];
    __shared__ int sbase;
    int bid = blockIdx.x;
    int t = threadIdx.x, lane = t & 31, wid = t >> 5;

    if (bid < nbe) {
        // ---- degree atomics ----
        int i = bid * 256 + t;
        if (i < e) {
            atomicAdd(&g_deg_out[src[i]], 1);
            atomicAdd(&g_deg_in[dst[i]], 1);
        }
        __threadfence();
        __syncthreads();
        if (t == 0) atomicAdd(&g_deg_done, 1u);
        return;
    }
    if (bid == nbe) {
        // ---- W1^T fp16 image ----
        __half* img = g_w1img;
#pragma unroll
        for (int i = 0; i < 16; ++i) {
            int idx = t + 256 * i;
            int k = idx >> 5, c4 = idx & 31;
            float4 v = ((const float4*)W1)[k * 32 + c4];
            float vv[4] = {v.x, v.y, v.z, v.w};
#pragma unroll
            for (int j = 0; j < 4; ++j)
                img[(c4 * 4 + j) * LDA + k] = __float2half_rn(vv[j]);
        }
        return;
    }
    if (bid < nbe + 1 + nbscan) {
        // ---- scan block (waits for all deg blocks) ----
        int sb = bid - (nbe + 1);
        if (t == 0) {
            while (*(volatile unsigned*)&g_deg_done < (unsigned)nbe) __nanosleep(128);
        }
        __syncthreads();

        int i = sb * 256 + t;
        int v = (i < n) ? g_deg_in[i] : 0;
        // block sum -> publish (value+1; word is its own flag)
        {
            int bs = v;
            for (int o = 16; o; o >>= 1) bs += __shfl_xor_sync(0xffffffffu, bs, o);
            if (lane == 0) ws[wid] = bs;
            __syncthreads();
            if (t == 0) {
                int s = 0;
                for (int j = 0; j < 8; ++j) s += ws[j];
                atomicExch(&g_partial[sb], s + 1);
            }
        }
        // lookback over predecessors
        int accp = 0;
        if (t < sb) {
            volatile int* p = g_partial + t;
            int pv;
            do { pv = *p; } while (pv == 0);
            accp = pv - 1;
        }
        for (int o = 16; o; o >>= 1) accp += __shfl_xor_sync(0xffffffffu, accp, o);
        if (lane == 0) ws2[wid] = accp;
        __syncthreads();
        if (t == 0) {
            int s = 0;
            for (int j = 0; j < 8; ++j) s += ws2[j];
            sbase = s;
        }
        __syncthreads();
        int base = sbase;
        __syncthreads();
        // local exclusive scan
        int x = v;
        for (int o = 1; o < 32; o <<= 1) {
            int y = __shfl_up_sync(0xffffffffu, x, o);
            if (lane >= o) x += y;
        }
        if (lane == 31) ws[wid] = x;
        __syncthreads();
        if (wid == 0 && lane < 8) {
            int s = ws[lane];
            for (int o = 1; o < 8; o <<= 1) {
                int y = __shfl_up_sync(0xffu, s, o);
                if (lane >= o) s += y;
            }
            ws[lane] = s;
        }
        __syncthreads();
        int wbase = (wid > 0) ? ws[wid - 1] : 0;
        if (i < n) {
            int ex = base + wbase + x - v;
            g_off[i] = ex;
            g_cursor[i] = ex;
            int a = g_deg_out[i];
            g_norm_src[i] = (a > 0) ? rsqrtf((float)a) : 0.f;
            g_norm_dst[i] = (v > 0) ? rsqrtf((float)v) : 0.f;
        }
        __threadfence();
        __syncthreads();
        if (t == 0) atomicAdd(&g_scan_done, 1u);
        return;
    }
    // ---- fill block (waits for all scan blocks) ----
    {
        int fb = bid - (nbe + 1 + nbscan);
        if (t == 0) {
            while (*(volatile unsigned*)&g_scan_done < (unsigned)nbscan) __nanosleep(128);
        }
        __syncthreads();
        if (fb == 0) g_partial[t] = 0;   // reset flags for next replay
        int i = fb * 256 + t;
        if (i < e) {
            int p = atomicAdd(&g_cursor[dst[i]], 1);
            g_csr_src[p] = src[i];
        }
    }
}

// ---------------- GEMM1 via mma.sync fp16 + ldmatrix (pure gemm) -----------
__device__ __forceinline__ void mma16816(float* c, const uint32_t* a, uint32_t b0, uint32_t b1) {
    asm volatile(
        "mma.sync.aligned.m16n8k16.row.col.f32.f16.f16.f32 "
        "{%0,%1,%2,%3}, {%4,%5,%6,%7}, {%8,%9}, {%0,%1,%2,%3};"
        : "+f"(c[0]), "+f"(c[1]), "+f"(c[2]), "+f"(c[3])
        : "r"(a[0]), "r"(a[1]), "r"(a[2]), "r"(a[3]), "r"(b0), "r"(b1));
}
__device__ __forceinline__ void ldsm4(uint32_t& r0, uint32_t& r1, uint32_t& r2, uint32_t& r3,
                                      uint32_t addr) {
    asm volatile("ldmatrix.sync.aligned.m8n8.x4.shared.b16 {%0,%1,%2,%3}, [%4];"
                 : "=r"(r0), "=r"(r1), "=r"(r2), "=r"(r3) : "r"(addr));
}

__global__ void __launch_bounds__(256, 2)
k_gemm1t(const float* __restrict__ X, int n) {
    extern __shared__ __half sm[];
    __half* As = sm;              // [128][LDA] (m x k)
    __half* Bs = sm + 128 * LDA;  // [128][LDA] = W1^T (n x k)
    int t = threadIdx.x;
    int row0 = blockIdx.x * 128;

    {
        const uint4* wi = (const uint4*)g_w1img;
        uint4* bs4 = (uint4*)Bs;
#pragma unroll
        for (int i = 0; i < 9; ++i) {
            int idx = t + 256 * i;
            if (idx < (128 * LDA * 2) / 16) bs4[idx] = wi[idx];
        }
    }
#pragma unroll
    for (int i = 0; i < 16; ++i) {
        int idx = t + 256 * i;
        int r = idx >> 5, c4 = idx & 31;
        float4 v = make_float4(0.f, 0.f, 0.f, 0.f);
        int g = row0 + r;
        if (g < n) v = ((const float4*)X)[g * 32 + c4];
        __half2 p0 = __floats2half2_rn(v.x, v.y);
        __half2 p1 = __floats2half2_rn(v.z, v.w);
        *(uint2*)(As + r * LDA + c4 * 4) =
            make_uint2(*(uint32_t*)&p0, *(uint32_t*)&p1);
    }
    __syncthreads();

    int wid = t >> 5, lane = t & 31;
    int m0 = (wid & 3) * 32;
    int n0 = (wid >> 2) * 64;
    int lr = lane >> 2;
    int lc = (lane & 3) * 2;
    int lrow = lane & 15;
    int lkb  = (lane >> 4) * 8;

    uint32_t sA = (uint32_t)__cvta_generic_to_shared(As);
    uint32_t sB = (uint32_t)__cvta_generic_to_shared(Bs);

    float acc[2][8][4];
#pragma unroll
    for (int mt = 0; mt < 2; ++mt)
#pragma unroll
        for (int nt = 0; nt < 8; ++nt)
#pragma unroll
            for (int q = 0; q < 4; ++q) acc[mt][nt][q] = 0.f;

#pragma unroll
    for (int k0 = 0; k0 < 128; k0 += 16) {
        uint32_t a[2][4];
#pragma unroll
        for (int mt = 0; mt < 2; ++mt) {
            uint32_t addr = sA + (uint32_t)(((m0 + mt * 16 + lrow) * LDA + k0 + lkb) * 2);
            ldsm4(a[mt][0], a[mt][1], a[mt][2], a[mt][3], addr);
        }
        uint32_t bf[4][4];
#pragma unroll
        for (int ntp = 0; ntp < 4; ++ntp) {
            uint32_t addr = sB + (uint32_t)(((n0 + ntp * 16 + lrow) * LDA + k0 + lkb) * 2);
            ldsm4(bf[ntp][0], bf[ntp][1], bf[ntp][2], bf[ntp][3], addr);
        }
#pragma unroll
        for (int ntp = 0; ntp < 4; ++ntp) {
            mma16816(acc[0][2 * ntp],     a[0], bf[ntp][0], bf[ntp][2]);
            mma16816(acc[1][2 * ntp],     a[1], bf[ntp][0], bf[ntp][2]);
            mma16816(acc[0][2 * ntp + 1], a[0], bf[ntp][1], bf[ntp][3]);
            mma16816(acc[1][2 * ntp + 1], a[1], bf[ntp][1], bf[ntp][3]);
        }
    }

#pragma unroll
    for (int mt = 0; mt < 2; ++mt) {
        int r0 = row0 + m0 + mt * 16 + lr;
        int r1 = r0 + 8;
        float s0 = (r0 < n) ? g_norm_src[r0] : 0.f;
        float s1 = (r1 < n) ? g_norm_src[r1] : 0.f;
#pragma unroll
        for (int nt = 0; nt < 8; ++nt) {
            int col = n0 + nt * 8 + lc;
            if (r0 < n)
                *(__half2*)(g_h1 + (size_t)r0 * 128 + col) =
                    __floats2half2_rn(acc[mt][nt][0] * s0, acc[mt][nt][1] * s0);
            if (r1 < n)
                *(__half2*)(g_h1 + (size_t)r1 * 128 + col) =
                    __floats2half2_rn(acc[mt][nt][2] * s1, acc[mt][nt][3] * s1);
        }
    }
}

// ------- agg1: warp per dst node; pairwise HADD2 then fp32 accumulate -------
__global__ void k_agg1(const float* __restrict__ b1, int n) {
    int w = (blockIdx.x * blockDim.x + threadIdx.x) >> 5;
    int lane = threadIdx.x & 31;
    if (w >= n) return;
    int s = g_off[w];
    int e = s + g_deg_in[w];
    const uint2* H = (const uint2*)g_h1;   // row = 32 uint2 (4 halves each)
    float4 acc = make_float4(0.f, 0.f, 0.f, 0.f);
    int i = s;
    for (; i + 4 <= e; i += 4) {
        int s0 = g_csr_src[i];
        int s1 = g_csr_src[i + 1];
        int s2 = g_csr_src[i + 2];
        int s3 = g_csr_src[i + 3];
        uint2 v0 = H[s0 * 32 + lane];
        uint2 v1 = H[s1 * 32 + lane];
        uint2 v2 = H[s2 * 32 + lane];
        uint2 v3 = H[s3 * 32 + lane];
        __half2 p0x = __hadd2(*(__half2*)&v0.x, *(__half2*)&v1.x);
        __half2 p0y = __hadd2(*(__half2*)&v0.y, *(__half2*)&v1.y);
        __half2 p1x = __hadd2(*(__half2*)&v2.x, *(__half2*)&v3.x);
        __half2 p1y = __hadd2(*(__half2*)&v2.y, *(__half2*)&v3.y);
        float2 f0x = __half22float2(p0x);
        float2 f0y = __half22float2(p0y);
        float2 f1x = __half22float2(p1x);
        float2 f1y = __half22float2(p1y);
        acc.x += f0x.x + f1x.x;
        acc.y += f0x.y + f1x.y;
        acc.z += f0y.x + f1y.x;
        acc.w += f0y.y + f1y.y;
    }
    if (i + 2 <= e) {
        int s0 = g_csr_src[i];
        int s1 = g_csr_src[i + 1];
        uint2 v0 = H[s0 * 32 + lane];
        uint2 v1 = H[s1 * 32 + lane];
        __half2 px = __hadd2(*(__half2*)&v0.x, *(__half2*)&v1.x);
        __half2 py = __hadd2(*(__half2*)&v0.y, *(__half2*)&v1.y);
        float2 fx = __half22float2(px);
        float2 fy = __half22float2(py);
        acc.x += fx.x; acc.y += fx.y; acc.z += fy.x; acc.w += fy.y;
        i += 2;
    }
    if (i < e) {
        int s0 = g_csr_src[i];
        uint2 v0 = H[s0 * 32 + lane];
        float2 a0 = __half22float2(*(__half2*)&v0.x);
        float2 a1 = __half22float2(*(__half2*)&v0.y);
        acc.x += a0.x; acc.y += a0.y; acc.z += a1.x; acc.w += a1.y;
    }
    float nd = g_norm_dst[w];
    float4 bb = ((const float4*)b1)[lane];
    float4 o;
    o.x = fmaxf(fmaf(acc.x, nd, bb.x), 0.f);
    o.y = fmaxf(fmaf(acc.y, nd, bb.y), 0.f);
    o.z = fmaxf(fmaf(acc.z, nd, bb.z), 0.f);
    o.w = fmaxf(fmaf(acc.w, nd, bb.w), 0.f);
    ((float4*)g_h2)[w * 32 + lane] = o;
}

// ---------------- GEMM2 ----------------
__global__ void k_gemm2(const float* __restrict__ W2, int n) {
    __shared__ float hs[32 * HP];
    __shared__ float ws[128 * 8];
    int t = threadIdx.x;
    int n0 = blockIdx.x * 32;
#pragma unroll
    for (int i = 0; i < 4; ++i) {
        int idx = t + 256 * i;
        int r = idx >> 5, c4 = idx & 31;
        float4 v = make_float4(0.f, 0.f, 0.f, 0.f);
        if (n0 + r < n) v = ((const float4*)g_h2)[(n0 + r) * 32 + c4];
        *(float4*)(hs + r * HP + c4 * 4) = v;
    }
    ((float4*)ws)[t] = ((const float4*)W2)[t];
    __syncthreads();
    int node = t >> 3, j = t & 7;
    int gn = n0 + node;
    float acc = 0.f;
#pragma unroll 8
    for (int k = 0; k < 128; ++k)
        acc = fmaf(hs[node * HP + k], ws[k * 8 + j], acc);
    if (gn < n) g_h3[gn * 8 + j] = acc * g_norm_src[gn];
}

// ---------------- agg2 (separate, coalesced) ----------------
__global__ void k_agg2(const float* __restrict__ b2, int n) {
    int idx = blockIdx.x * blockDim.x + threadIdx.x;
    int node = idx >> 3, f = idx & 7;
    if (node >= n) return;
    int s = g_off[node];
    int e = s + g_deg_in[node];
    float acc = 0.f;
    for (int i = s; i < e; ++i)
        acc += g_h3[g_csr_src[i] * 8 + f];
    g_nodeout[node * 8 + f] = fmaf(acc, g_norm_dst[node], b2[f]);
}

// ---- k_pool: mean pooling + state restore tail (deg arrays, counters) ------
__global__ void k_pool(const int* __restrict__ gids, float* __restrict__ out, int n) {
    __shared__ int sse[2];
    __shared__ float red[256 * 8];
    int g = blockIdx.x;
    int t = threadIdx.x;
    if (t == 0) {
        int lo = 0, hi = n;
        while (lo < hi) { int m = (lo + hi) >> 1; if (gids[m] < g) lo = m + 1; else hi = m; }
        sse[0] = lo;
        lo = 0; hi = n;
        while (lo < hi) { int m = (lo + hi) >> 1; if (gids[m] <= g) lo = m + 1; else hi = m; }
        sse[1] = lo;
    }
    __syncthreads();
    int s = sse[0], e = sse[1];
    float acc[8] = {};
    for (int i = s + t; i < e; i += 256) {
#pragma unroll
        for (int f = 0; f < 8; ++f) acc[f] += g_nodeout[i * 8 + f];
    }
#pragma unroll
    for (int f = 0; f < 8; ++f) red[t * 8 + f] = acc[f];
    __syncthreads();
    for (int d = 128; d > 0; d >>= 1) {
        if (t < d) {
#pragma unroll
            for (int f = 0; f < 8; ++f)
                red[t * 8 + f] += red[(t + d) * 8 + f];
        }
        __syncthreads();
    }
    if (t < 8) {
        float cnt = (float)(e - s);
        out[g * 8 + t] = red[t] / fmaxf(cnt, 1.f);
    }
    // restore state for next replay
    for (int i = s + t; i < e; i += 256) {
        g_deg_in[i] = 0;
        g_deg_out[i] = 0;
    }
    if (g == 0 && t == 0) {
        g_deg_done = 0u;
        g_scan_done = 0u;
    }
}

// ---------------- launch ----------------
extern "C" void kernel_launch(void* const* d_in, const int* in_sizes, int n_in,
                              void* d_out, int out_size) {
    const float* x   = (const float*)d_in[0];
    const float* W1  = (const float*)d_in[1];
    const float* b1  = (const float*)d_in[2];
    const float* W2  = (const float*)d_in[3];
    const float* b2  = (const float*)d_in[4];
    const int*   src = (const int*)d_in[5];
    const int*   dst = (const int*)d_in[6];
    const int*   gid = (const int*)d_in[7];
    int n  = in_sizes[7];
    int e  = in_sizes[5];
    int ng = out_size / 8;
    float* out = (float*)d_out;

    int nbe = (e + 255) / 256;
    int nbscan = (n + 255) / 256;
    int ngemm = (n + 127) / 128;

    k_graph<<<nbe + 1 + nbscan + nbe, 256>>>(W1, src, dst, n, e, nbe, nbscan);

    int smem = 2 * 128 * LDA * (int)sizeof(__half);
    cudaFuncSetAttribute(k_gemm1t, cudaFuncAttributeMaxDynamicSharedMemorySize, smem);
    k_gemm1t<<<ngemm, 256, smem>>>(x, n);

    k_agg1<<<(n * 32 + 255) / 256, 256>>>(b1, n);
    k_gemm2<<<(n + 31) / 32, 256>>>(W2, n);
    k_agg2<<<(n * 8 + 255) / 256, 256>>>(b2, n);
    k_pool<<<ng, 256>>>(gid, out, n);
}

// round 16
// speedup vs baseline: 1.0822x; 1.0822x over previous
#include <cuda_runtime.h>
#include <cuda_fp16.h>
#include <cstdint>

#define MAXN 50000
#define MAXE 800000
#define LDA  136    // fp16 row stride for A/B smem tiles (conflict-free)

// ---------------- scratch (device globals; no allocation allowed) ----------
__device__ __align__(16) __half g_h1[MAXN * 128];  // (x@W1)*norm_src, fp16
__device__ __align__(16) __half g_h2[MAXN * 128];  // relu(...) fp16
__device__ __align__(16) float g_h3[MAXN * 8];
__device__ __align__(16) float g_nodeout[MAXN * 8];
__device__ __align__(16) __half g_w1img[128 * LDA];  // W1^T fp16 [n][k], padded
__device__ int   g_deg_out[MAXN];   // zeroed by k_pool tail each run
__device__ int   g_deg_in[MAXN];    // zeroed by k_pool tail each run
__device__ float g_norm_src[MAXN];
__device__ float g_norm_dst[MAXN];
__device__ int   g_off[MAXN];
__device__ int   g_cursor[MAXN];
__device__ int   g_csr_src[MAXE];
__device__ int   g_partial[256];    // scan flags: value+1; zeroed each run

// ---- k_deg: degree atomics (deg arrays arrive zeroed) + W1 image block ----
__global__ void k_deg(const float* __restrict__ W1, const int* __restrict__ src,
                      const int* __restrict__ dst, int e, int nbe) {
    if ((int)blockIdx.x == nbe) {
        int t = threadIdx.x;
        __half* img = g_w1img;
#pragma unroll
        for (int i = 0; i < 16; ++i) {
            int idx = t + 256 * i;          // 4096 float4 = 128 k-rows x 32
            int k = idx >> 5, c4 = idx & 31;
            float4 v = ((const float4*)W1)[k * 32 + c4];
            float vv[4] = {v.x, v.y, v.z, v.w};
#pragma unroll
            for (int j = 0; j < 4; ++j)
                img[(c4 * 4 + j) * LDA + k] = __float2half_rn(vv[j]);
        }
        return;
    }
    int i = blockIdx.x * blockDim.x + threadIdx.x;
    if (i < e) {
        atomicAdd(&g_deg_out[src[i]], 1);
        atomicAdd(&g_deg_in[dst[i]], 1);
    }
}

// ---- k_scan: one-pass scan (publish partial+1, poll predecessors) + norms --
__global__ void k_scan(int n) {
    __shared__ int ws[8];
    __shared__ int ws2[8];
    __shared__ int sbase;
    int t = threadIdx.x, lane = t & 31, wid = t >> 5;
    int bid = blockIdx.x;
    int i = bid * 256 + t;
    int v = (i < n) ? g_deg_in[i] : 0;

    {
        int bs = v;
        for (int o = 16; o; o >>= 1) bs += __shfl_xor_sync(0xffffffffu, bs, o);
        if (lane == 0) ws[wid] = bs;
        __syncthreads();
        if (t == 0) {
            int s = 0;
            for (int j = 0; j < 8; ++j) s += ws[j];
            atomicExch(&g_partial[bid], s + 1);
        }
    }

    int accp = 0;
    if (t < bid) {
        volatile int* p = g_partial + t;
        int pv;
        do { pv = *p; } while (pv == 0);
        accp = pv - 1;
    }
    for (int o = 16; o; o >>= 1) accp += __shfl_xor_sync(0xffffffffu, accp, o);
    if (lane == 0) ws2[wid] = accp;
    __syncthreads();
    if (t == 0) {
        int s = 0;
        for (int j = 0; j < 8; ++j) s += ws2[j];
        sbase = s;
    }
    __syncthreads();
    int base = sbase;
    __syncthreads();

    int x = v;
    for (int o = 1; o < 32; o <<= 1) {
        int y = __shfl_up_sync(0xffffffffu, x, o);
        if (lane >= o) x += y;
    }
    if (lane == 31) ws[wid] = x;
    __syncthreads();
    if (wid == 0 && lane < 8) {
        int s = ws[lane];
        for (int o = 1; o < 8; o <<= 1) {
            int y = __shfl_up_sync(0xffu, s, o);
            if (lane >= o) s += y;
        }
        ws[lane] = s;
    }
    __syncthreads();
    int wbase = (wid > 0) ? ws[wid - 1] : 0;
    if (i < n) {
        int ex = base + wbase + x - v;
        g_off[i] = ex;
        g_cursor[i] = ex;
        int a = g_deg_out[i];
        g_norm_src[i] = (a > 0) ? rsqrtf((float)a) : 0.f;
        g_norm_dst[i] = (v > 0) ? rsqrtf((float)v) : 0.f;
    }
}

// ---------------- GEMM1 (mma.sync fp16 + ldmatrix) + CSR-fill tail blocks --
__device__ __forceinline__ void mma16816(float* c, const uint32_t* a, uint32_t b0, uint32_t b1) {
    asm volatile(
        "mma.sync.aligned.m16n8k16.row.col.f32.f16.f16.f32 "
        "{%0,%1,%2,%3}, {%4,%5,%6,%7}, {%8,%9}, {%0,%1,%2,%3};"
        : "+f"(c[0]), "+f"(c[1]), "+f"(c[2]), "+f"(c[3])
        : "r"(a[0]), "r"(a[1]), "r"(a[2]), "r"(a[3]), "r"(b0), "r"(b1));
}
__device__ __forceinline__ void ldsm4(uint32_t& r0, uint32_t& r1, uint32_t& r2, uint32_t& r3,
                                      uint32_t addr) {
    asm volatile("ldmatrix.sync.aligned.m8n8.x4.shared.b16 {%0,%1,%2,%3}, [%4];"
                 : "=r"(r0), "=r"(r1), "=r"(r2), "=r"(r3) : "r"(addr));
}

__global__ void __launch_bounds__(256, 2)
k_gemm1t(const float* __restrict__ X, const int* __restrict__ src,
         const int* __restrict__ dst, int n, int e, int ngemm) {
    // -------- fill tail blocks: CSR fill + scan-flag reset (independent) ----
    if ((int)blockIdx.x >= ngemm) {
        int fb = blockIdx.x - ngemm;
        if (fb == 0) g_partial[threadIdx.x] = 0;
        int i = fb * 256 + threadIdx.x;
        if (i < e) {
            int p = atomicAdd(&g_cursor[dst[i]], 1);
            g_csr_src[p] = src[i];
        }
        return;
    }

    extern __shared__ __half sm[];
    __half* As = sm;              // [128][LDA] (m x k)
    __half* Bs = sm + 128 * LDA;  // [128][LDA] = W1^T (n x k)
    int t = threadIdx.x;
    int row0 = blockIdx.x * 128;

    {
        const uint4* wi = (const uint4*)g_w1img;
        uint4* bs4 = (uint4*)Bs;
#pragma unroll
        for (int i = 0; i < 9; ++i) {
            int idx = t + 256 * i;
            if (idx < (128 * LDA * 2) / 16) bs4[idx] = wi[idx];
        }
    }
#pragma unroll
    for (int i = 0; i < 16; ++i) {
        int idx = t + 256 * i;
        int r = idx >> 5, c4 = idx & 31;
        float4 v = make_float4(0.f, 0.f, 0.f, 0.f);
        int g = row0 + r;
        if (g < n) v = ((const float4*)X)[g * 32 + c4];
        __half2 p0 = __floats2half2_rn(v.x, v.y);
        __half2 p1 = __floats2half2_rn(v.z, v.w);
        *(uint2*)(As + r * LDA + c4 * 4) =
            make_uint2(*(uint32_t*)&p0, *(uint32_t*)&p1);
    }
    __syncthreads();

    int wid = t >> 5, lane = t & 31;
    int m0 = (wid & 3) * 32;
    int n0 = (wid >> 2) * 64;
    int lr = lane >> 2;
    int lc = (lane & 3) * 2;
    int lrow = lane & 15;
    int lkb  = (lane >> 4) * 8;

    uint32_t sA = (uint32_t)__cvta_generic_to_shared(As);
    uint32_t sB = (uint32_t)__cvta_generic_to_shared(Bs);

    float acc[2][8][4];
#pragma unroll
    for (int mt = 0; mt < 2; ++mt)
#pragma unroll
        for (int nt = 0; nt < 8; ++nt)
#pragma unroll
            for (int q = 0; q < 4; ++q) acc[mt][nt][q] = 0.f;

#pragma unroll
    for (int k0 = 0; k0 < 128; k0 += 16) {
        uint32_t a[2][4];
#pragma unroll
        for (int mt = 0; mt < 2; ++mt) {
            uint32_t addr = sA + (uint32_t)(((m0 + mt * 16 + lrow) * LDA + k0 + lkb) * 2);
            ldsm4(a[mt][0], a[mt][1], a[mt][2], a[mt][3], addr);
        }
        uint32_t bf[4][4];
#pragma unroll
        for (int ntp = 0; ntp < 4; ++ntp) {
            uint32_t addr = sB + (uint32_t)(((n0 + ntp * 16 + lrow) * LDA + k0 + lkb) * 2);
            ldsm4(bf[ntp][0], bf[ntp][1], bf[ntp][2], bf[ntp][3], addr);
        }
#pragma unroll
        for (int ntp = 0; ntp < 4; ++ntp) {
            mma16816(acc[0][2 * ntp],     a[0], bf[ntp][0], bf[ntp][2]);
            mma16816(acc[1][2 * ntp],     a[1], bf[ntp][0], bf[ntp][2]);
            mma16816(acc[0][2 * ntp + 1], a[0], bf[ntp][1], bf[ntp][3]);
            mma16816(acc[1][2 * ntp + 1], a[1], bf[ntp][1], bf[ntp][3]);
        }
    }

#pragma unroll
    for (int mt = 0; mt < 2; ++mt) {
        int r0 = row0 + m0 + mt * 16 + lr;
        int r1 = r0 + 8;
        float s0 = (r0 < n) ? g_norm_src[r0] : 0.f;
        float s1 = (r1 < n) ? g_norm_src[r1] : 0.f;
#pragma unroll
        for (int nt = 0; nt < 8; ++nt) {
            int col = n0 + nt * 8 + lc;
            if (r0 < n)
                *(__half2*)(g_h1 + (size_t)r0 * 128 + col) =
                    __floats2half2_rn(acc[mt][nt][0] * s0, acc[mt][nt][1] * s0);
            if (r1 < n)
                *(__half2*)(g_h1 + (size_t)r1 * 128 + col) =
                    __floats2half2_rn(acc[mt][nt][2] * s1, acc[mt][nt][3] * s1);
        }
    }
}

// ------- agg1: warp per dst node; pairwise HADD2, fp32 accum, fp16 h2 out ---
__global__ void k_agg1(const float* __restrict__ b1, int n) {
    int w = (blockIdx.x * blockDim.x + threadIdx.x) >> 5;
    int lane = threadIdx.x & 31;
    if (w >= n) return;
    int s = g_off[w];
    int e = s + g_deg_in[w];
    const uint2* H = (const uint2*)g_h1;   // row = 32 uint2 (4 halves each)
    float4 acc = make_float4(0.f, 0.f, 0.f, 0.f);
    int i = s;
    for (; i + 4 <= e; i += 4) {
        int s0 = g_csr_src[i];
        int s1 = g_csr_src[i + 1];
        int s2 = g_csr_src[i + 2];
        int s3 = g_csr_src[i + 3];
        uint2 v0 = H[s0 * 32 + lane];
        uint2 v1 = H[s1 * 32 + lane];
        uint2 v2 = H[s2 * 32 + lane];
        uint2 v3 = H[s3 * 32 + lane];
        __half2 p0x = __hadd2(*(__half2*)&v0.x, *(__half2*)&v1.x);
        __half2 p0y = __hadd2(*(__half2*)&v0.y, *(__half2*)&v1.y);
        __half2 p1x = __hadd2(*(__half2*)&v2.x, *(__half2*)&v3.x);
        __half2 p1y = __hadd2(*(__half2*)&v2.y, *(__half2*)&v3.y);
        float2 f0x = __half22float2(p0x);
        float2 f0y = __half22float2(p0y);
        float2 f1x = __half22float2(p1x);
        float2 f1y = __half22float2(p1y);
        acc.x += f0x.x + f1x.x;
        acc.y += f0x.y + f1x.y;
        acc.z += f0y.x + f1y.x;
        acc.w += f0y.y + f1y.y;
    }
    if (i + 2 <= e) {
        int s0 = g_csr_src[i];
        int s1 = g_csr_src[i + 1];
        uint2 v0 = H[s0 * 32 + lane];
        uint2 v1 = H[s1 * 32 + lane];
        __half2 px = __hadd2(*(__half2*)&v0.x, *(__half2*)&v1.x);
        __half2 py = __hadd2(*(__half2*)&v0.y, *(__half2*)&v1.y);
        float2 fx = __half22float2(px);
        float2 fy = __half22float2(py);
        acc.x += fx.x; acc.y += fx.y; acc.z += fy.x; acc.w += fy.y;
        i += 2;
    }
    if (i < e) {
        int s0 = g_csr_src[i];
        uint2 v0 = H[s0 * 32 + lane];
        float2 a0 = __half22float2(*(__half2*)&v0.x);
        float2 a1 = __half22float2(*(__half2*)&v0.y);
        acc.x += a0.x; acc.y += a0.y; acc.z += a1.x; acc.w += a1.y;
    }
    float nd = g_norm_dst[w];
    float4 bb = ((const float4*)b1)[lane];
    float ox = fmaxf(fmaf(acc.x, nd, bb.x), 0.f);
    float oy = fmaxf(fmaf(acc.y, nd, bb.y), 0.f);
    float oz = fmaxf(fmaf(acc.z, nd, bb.z), 0.f);
    float ow = fmaxf(fmaf(acc.w, nd, bb.w), 0.f);
    __half2 h01 = __floats2half2_rn(ox, oy);
    __half2 h23 = __floats2half2_rn(oz, ow);
    ((uint2*)g_h2)[w * 32 + lane] = make_uint2(*(uint32_t*)&h01, *(uint32_t*)&h23);
}

// ------ GEMM2: fp16 h2 stream, transposed-W2 smem, vectorized loads --------
__global__ void k_gemm2(const float* __restrict__ W2, int n) {
    __shared__ uint2  hs[32 * 33];     // 32 nodes x 32 uint2 (4 halves) + pad
    __shared__ float  wst[8 * 132];    // W2^T [j][k], float4-aligned rows
    int t = threadIdx.x;
    int n0 = blockIdx.x * 32;

    // load W2 transposed: W2[k][j] -> wst[j*132 + k]
    for (int idx = t; idx < 1024; idx += 256) {
        int k = idx >> 3, j = idx & 7;
        wst[j * 132 + k] = W2[idx];
    }
    // stage 32 fp16 rows of h2
    const uint2* H2 = (const uint2*)g_h2;
#pragma unroll
    for (int i = 0; i < 2; ++i) {
        int idx = t + 256 * i;          // 512 uint2 = 32 rows x 16? no: 32 rows x 32/2
        int r = idx >> 5, c = idx & 31;  // wait 512 = 16 rows... fix: 32 rows x 32 cols = 1024
        (void)r; (void)c;
    }
    for (int idx = t; idx < 32 * 32; idx += 256) {
        int r = idx >> 5, c = idx & 31;
        uint2 v = make_uint2(0u, 0u);
        if (n0 + r < n) v = H2[(size_t)(n0 + r) * 32 + c];
        hs[r * 33 + c] = v;
    }
    __syncthreads();

    int node = t >> 3, j = t & 7;
    int gn = n0 + node;
    float acc = 0.f;
#pragma unroll
    for (int k4 = 0; k4 < 32; ++k4) {
        uint2 hv = hs[node * 33 + k4];
        float2 f0 = __half22float2(*(__half2*)&hv.x);
        float2 f1 = __half22float2(*(__half2*)&hv.y);
        float4 w = *(const float4*)(wst + j * 132 + k4 * 4);
        acc = fmaf(f0.x, w.x, acc);
        acc = fmaf(f0.y, w.y, acc);
        acc = fmaf(f1.x, w.z, acc);
        acc = fmaf(f1.y, w.w, acc);
    }
    if (gn < n) g_h3[gn * 8 + j] = acc * g_norm_src[gn];
}

// ---------------- agg2 (separate, coalesced) ----------------
__global__ void k_agg2(const float* __restrict__ b2, int n) {
    int idx = blockIdx.x * blockDim.x + threadIdx.x;
    int node = idx >> 3, f = idx & 7;
    if (node >= n) return;
    int s = g_off[node];
    int e = s + g_deg_in[node];
    float acc = 0.f;
    for (int i = s; i < e; ++i)
        acc += g_h3[g_csr_src[i] * 8 + f];
    g_nodeout[node * 8 + f] = fmaf(acc, g_norm_dst[node], b2[f]);
}

// ---- k_pool: mean pooling + deg-array restore tail ----
__global__ void k_pool(const int* __restrict__ gids, float* __restrict__ out, int n) {
    __shared__ int sse[2];
    __shared__ float red[256 * 8];
    int g = blockIdx.x;
    int t = threadIdx.x;
    if (t == 0) {
        int lo = 0, hi = n;
        while (lo < hi) { int m = (lo + hi) >> 1; if (gids[m] < g) lo = m + 1; else hi = m; }
        sse[0] = lo;
        lo = 0; hi = n;
        while (lo < hi) { int m = (lo + hi) >> 1; if (gids[m] <= g) lo = m + 1; else hi = m; }
        sse[1] = lo;
    }
    __syncthreads();
    int s = sse[0], e = sse[1];
    float acc[8] = {};
    for (int i = s + t; i < e; i += 256) {
#pragma unroll
        for (int f = 0; f < 8; ++f) acc[f] += g_nodeout[i * 8 + f];
    }
#pragma unroll
    for (int f = 0; f < 8; ++f) red[t * 8 + f] = acc[f];
    __syncthreads();
    for (int d = 128; d > 0; d >>= 1) {
        if (t < d) {
#pragma unroll
            for (int f = 0; f < 8; ++f)
                red[t * 8 + f] += red[(t + d) * 8 + f];
        }
        __syncthreads();
    }
    if (t < 8) {
        float cnt = (float)(e - s);
        out[g * 8 + t] = red[t] / fmaxf(cnt, 1.f);
    }
    // restore deg arrays to zero for the next run (graph ranges partition [0,n))
    for (int i = s + t; i < e; i += 256) {
        g_deg_in[i] = 0;
        g_deg_out[i] = 0;
    }
}

// ---------------- launch ----------------
extern "C" void kernel_launch(void* const* d_in, const int* in_sizes, int n_in,
                              void* d_out, int out_size) {
    const float* x   = (const float*)d_in[0];
    const float* W1  = (const float*)d_in[1];
    const float* b1  = (const float*)d_in[2];
    const float* W2  = (const float*)d_in[3];
    const float* b2  = (const float*)d_in[4];
    const int*   src = (const int*)d_in[5];
    const int*   dst = (const int*)d_in[6];
    const int*   gid = (const int*)d_in[7];
    int n  = in_sizes[7];
    int e  = in_sizes[5];
    int ng = out_size / 8;
    float* out = (float*)d_out;

    int nbe = (e + 255) / 256;
    int nbscan = (n + 255) / 256;
    int ngemm = (n + 127) / 128;

    k_deg<<<nbe + 1, 256>>>(W1, src, dst, e, nbe);
    k_scan<<<nbscan, 256>>>(n);

    int smem = 2 * 128 * LDA * (int)sizeof(__half);
    cudaFuncSetAttribute(k_gemm1t, cudaFuncAttributeMaxDynamicSharedMemorySize, smem);
    k_gemm1t<<<ngemm + nbe, 256, smem>>>(x, src, dst, n, e, ngemm);

    k_agg1<<<(n * 32 + 255) / 256, 256>>>(b1, n);
    k_gemm2<<<(n + 31) / 32, 256>>>(W2, n);
    k_agg2<<<(n * 8 + 255) / 256, 256>>>(b2, n);
    k_pool<<<ng, 256>>>(gid, out, n);
}